// round 9
// baseline (speedup 1.0000x reference)
#include <cuda_runtime.h>

#define T_LEN 2048
#define B_LEN 2048
#define HID   32
#define DF    8
#define DP    8
#define DS    24
#define WARPS_PER_CTA 7
#define NTHREADS (WARPS_PER_CTA * 32)
#define NCTAS 147      // 147*7 = 1029 warps; 1024 active (B/2)

typedef unsigned long long u64;

__device__ __forceinline__ float tanh_fast(float x) {
    float y; asm("tanh.approx.f32 %0, %1;" : "=f"(y) : "f"(x)); return y;
}
__device__ __forceinline__ u64 pk2(float w) {            // (w, w)
    u64 d; asm("mov.b64 %0, {%1, %1};" : "=l"(d) : "f"(w)); return d;
}
__device__ __forceinline__ u64 pack2(float lo, float hi) {
    u64 d; asm("mov.b64 %0, {%1, %2};" : "=l"(d) : "f"(lo), "f"(hi)); return d;
}
__device__ __forceinline__ void fma2(u64& a, u64 x, u64 w) {
    asm("fma.rn.f32x2 %0, %1, %2, %0;" : "+l"(a) : "l"(x), "l"(w));
}
__device__ __forceinline__ u64 add2(u64 a, u64 b) {
    u64 d; asm("add.rn.f32x2 %0, %1, %2;" : "=l"(d) : "l"(a), "l"(b)); return d;
}
__device__ __forceinline__ float2 unpk(u64 d) {
    float2 f; asm("mov.b64 {%0, %1}, %2;" : "=f"(f.x), "=f"(f.y) : "l"(d)); return f;
}

// Per-warp state: u64 = (batch b0, batch b1) pair.
struct __align__(16) WarpState {
    u64 hf[HID], hp[HID], hs0[HID], hs1[HID], hs2[HID];
    u64 xf[DF], xp[DP], xs[DS];
};

__global__ void __launch_bounds__(NTHREADS, 1)
chive_kernel(const float* __restrict__ frnn, const float* __restrict__ phrnn,
             const float* __restrict__ syl,
             const float* __restrict__ Wxf, const float* __restrict__ Whf,
             const float* __restrict__ bfv,
             const float* __restrict__ Wxp, const float* __restrict__ Whp,
             const float* __restrict__ bpv,
             const float* __restrict__ Wxs, const float* __restrict__ Whs,
             const float* __restrict__ bsv,
             const int* __restrict__ fclock, const int* __restrict__ pclock,
             const int* __restrict__ sfreq,
             float* __restrict__ out)
{
    __shared__ unsigned char flags_sm[T_LEN];
    __shared__ WarpState wst[WARPS_PER_CTA];
    __shared__ u64 whf2_s[HID * HID];   // pre-packed (w,w) f/p weights
    __shared__ u64 whp2_s[HID * HID];
    __shared__ u64 wxf2_s[DF * HID];
    __shared__ u64 wxp2_s[DP * HID];

    const int tid = threadIdx.x;
    for (int t = tid; t < T_LEN; t += NTHREADS) {
        int fl = ((t % (fclock[t] + 1)) == 0) ? 1 : 0;
        if ((t % (pclock[t] + 1)) == 0) fl |= 2;
        if (sfreq[t] == 1) fl |= 4;
        flags_sm[t] = (unsigned char)fl;
    }
    for (int i = tid; i < HID * HID; i += NTHREADS) {
        whf2_s[i] = pk2(Whf[i]);
        whp2_s[i] = pk2(Whp[i]);
    }
    for (int i = tid; i < DF * HID; i += NTHREADS) {
        wxf2_s[i] = pk2(Wxf[i]);
        wxp2_s[i] = pk2(Wxp[i]);
    }
    __syncthreads();

    const int warp = tid >> 5;
    const int lane = tid & 31;
    const int b0 = (blockIdx.x * WARPS_PER_CTA + warp) * 2;
    if (b0 >= B_LEN) return;    // after the only __syncthreads

    WarpState& S = wst[warp];
    S.hf[lane] = 0ull; S.hp[lane] = 0ull;
    S.hs0[lane] = 0ull; S.hs1[lane] = 0ull; S.hs2[lane] = 0ull;

    // s-cell weight columns pre-packed (w,w) in registers (lane = column).
    u64 wxs2[HID], whs2[HID];
    #pragma unroll
    for (int k = 0; k < HID; k++) {
        wxs2[k] = pk2(Wxs[k * HID + lane]);
        whs2[k] = pk2(Whs[k * HID + lane]);
    }
    const u64 bf2 = pk2(bfv[lane]), bp2 = pk2(bpv[lane]), bs2 = pk2(bsv[lane]);

    const bool lf = lane < DF, lp = lane < DP, ls = lane < DS;

    // Depth-3 unconditional input prefetch ring (registers).
    float Af0, Af1, Ap0, Ap1, As0, As1;
    float Bf0, Bf1, Bp0, Bp1, Bs0, Bs1;
    float Cf0, Cf1, Cp0, Cp1, Cs0, Cs1;

#define LOADSET(F0, F1, P0, P1, Q0, Q1, TT) do {                              \
        const float* pf_ = frnn  + ((size_t)(TT) * B_LEN + b0) * DF + lane;   \
        F0 = lf ? pf_[0] : 0.f;  F1 = lf ? pf_[DF] : 0.f;                     \
        const float* pp_ = phrnn + ((size_t)(TT) * B_LEN + b0) * DP + lane;   \
        P0 = lp ? pp_[0] : 0.f;  P1 = lp ? pp_[DP] : 0.f;                     \
        const float* ps_ = syl   + ((size_t)(TT) * B_LEN + b0) * DS + lane;   \
        Q0 = ls ? ps_[0] : 0.f;  Q1 = ls ? ps_[DS] : 0.f;                     \
    } while (0)

    LOADSET(Af0, Af1, Ap0, Ap1, As0, As1, 0);
    LOADSET(Bf0, Bf1, Bp0, Bp1, Bs0, Bs1, 1);
    LOADSET(Cf0, Cf1, Cp0, Cp1, Cs0, Cs1, 2);

    for (int t = 0; t < T_LEN; t++) {
        const int fl = flags_sm[t];

        if (fl) {
            if ((fl & 1) && lf) S.xf[lane] = pack2(Af0, Af1);
            if ((fl & 2) && lp) S.xp[lane] = pack2(Ap0, Ap1);
            if ((fl & 4) && ls) S.xs[lane] = pack2(As0, As1);
            __syncwarp();   // stage visible; also fences prior-step h/hs writes

            const bool wf = (fl & 1) != 0, wp = (fl & 2) != 0;
            u64 nhf = 0ull, nhp = 0ull;

            if (wf) {
                u64 a = bf2, c = 0ull;
                #pragma unroll
                for (int i = 0; i < DF; i++)
                    fma2(a, S.xf[i], wxf2_s[i * HID + lane]);
                #pragma unroll
                for (int k = 0; k < HID; k++)
                    fma2(c, S.hf[k], whf2_s[k * HID + lane]);
                const float2 u = unpk(add2(a, c));
                nhf = pack2(tanh_fast(u.x), tanh_fast(u.y));
            }
            if (wp) {
                u64 a = bp2, c = 0ull;
                #pragma unroll
                for (int i = 0; i < DP; i++)
                    fma2(a, S.xp[i], wxp2_s[i * HID + lane]);
                #pragma unroll
                for (int k = 0; k < HID; k++)
                    fma2(c, S.hp[k], whp2_s[k * HID + lane]);
                const float2 u = unpk(add2(a, c));
                nhp = pack2(tanh_fast(u.x), tanh_fast(u.y));
            }
            if (wf || wp) {
                __syncwarp();   // all lanes finished reading old hf/hp
                if (wf) S.hf[lane] = nhf;
                if (wp) S.hp[lane] = nhp;
                __syncwarp();   // new hf/hp visible for s-cell
            }

            if (fl & 4) {
                u64 a0 = bs2, c0 = 0ull;   // row0: x = hf
                u64 a1 = bs2, c1 = 0ull;   // row1: x = hp
                u64 a2 = bs2, c2 = 0ull;   // row2: x = xs
                #pragma unroll
                for (int k = 0; k < HID; k++) {
                    const u64 wx = wxs2[k], wh = whs2[k];
                    fma2(a0, S.hf[k],  wx);
                    fma2(c0, S.hs0[k], wh);
                    fma2(a1, S.hp[k],  wx);
                    fma2(c1, S.hs1[k], wh);
                    fma2(c2, S.hs2[k], wh);
                }
                #pragma unroll
                for (int k = 0; k < DS; k++)   // padded cols 24..31 are zero
                    fma2(a2, S.xs[k], wxs2[k]);
                const float2 u0 = unpk(add2(a0, c0));
                const float2 u1 = unpk(add2(a1, c1));
                const float2 u2 = unpk(add2(a2, c2));
                const u64 o0 = pack2(tanh_fast(u0.x), tanh_fast(u0.y));
                const u64 o1 = pack2(tanh_fast(u1.x), tanh_fast(u1.y));
                const u64 o2 = pack2(tanh_fast(u2.x), tanh_fast(u2.y));
                __syncwarp();   // all lanes finished reading old hs
                S.hs0[lane] = o0; S.hs1[lane] = o1; S.hs2[lane] = o2;
            }
        }

        // Rotate ring and issue unconditional loads for t+3.
        Af0 = Bf0; Af1 = Bf1; Ap0 = Bp0; Ap1 = Bp1; As0 = Bs0; As1 = Bs1;
        Bf0 = Cf0; Bf1 = Cf1; Bp0 = Cp0; Bp1 = Cp1; Bs0 = Cs0; Bs1 = Cs1;
        int tl = t + 3; if (tl >= T_LEN) tl = T_LEN - 1;
        LOADSET(Cf0, Cf1, Cp0, Cp1, Cs0, Cs1, tl);
    }
#undef LOADSET

    __syncwarp();
    // Emit final h_s [3, B, H]; lane j owns column j for both batches.
    const float2 r0 = unpk(S.hs0[lane]);
    const float2 r1 = unpk(S.hs1[lane]);
    const float2 r2 = unpk(S.hs2[lane]);
    out[((size_t)0 * B_LEN + b0)     * HID + lane] = r0.x;
    out[((size_t)0 * B_LEN + b0 + 1) * HID + lane] = r0.y;
    out[((size_t)1 * B_LEN + b0)     * HID + lane] = r1.x;
    out[((size_t)1 * B_LEN + b0 + 1) * HID + lane] = r1.y;
    out[((size_t)2 * B_LEN + b0)     * HID + lane] = r2.x;
    out[((size_t)2 * B_LEN + b0 + 1) * HID + lane] = r2.y;
}

extern "C" void kernel_launch(void* const* d_in, const int* in_sizes, int n_in,
                              void* d_out, int out_size) {
    (void)in_sizes; (void)n_in; (void)out_size;
    chive_kernel<<<NCTAS, NTHREADS>>>(
        (const float*)d_in[0],  (const float*)d_in[1],  (const float*)d_in[2],
        (const float*)d_in[3],  (const float*)d_in[4],  (const float*)d_in[5],
        (const float*)d_in[6],  (const float*)d_in[7],  (const float*)d_in[8],
        (const float*)d_in[9],  (const float*)d_in[10], (const float*)d_in[11],
        (const int*)d_in[12],   (const int*)d_in[13],   (const int*)d_in[14],
        (float*)d_out);
}

// round 12
// speedup vs baseline: 1.4863x; 1.4863x over previous
#include <cuda_runtime.h>

#define T_LEN 2048
#define B_LEN 2048
#define HID   32
#define DF    8
#define DP    8
#define DS    24
#define WARPS_PER_CTA 7
#define NTHREADS (WARPS_PER_CTA * 32)
#define NCTAS 147      // 147*7 = 1029 warps; 1024 active (B/2)

typedef unsigned long long u64;

__device__ __forceinline__ float tanh_fast(float x) {
    float y; asm("tanh.approx.f32 %0, %1;" : "=f"(y) : "f"(x)); return y;
}
__device__ __forceinline__ u64 pk2(float w) {            // (w, w)
    u64 d; asm("mov.b64 %0, {%1, %1};" : "=l"(d) : "f"(w)); return d;
}
__device__ __forceinline__ u64 pack2(float lo, float hi) {
    u64 d; asm("mov.b64 %0, {%1, %2};" : "=l"(d) : "f"(lo), "f"(hi)); return d;
}
__device__ __forceinline__ void fma2(u64& a, u64 x, u64 w) {
    asm("fma.rn.f32x2 %0, %1, %2, %0;" : "+l"(a) : "l"(x), "l"(w));
}
__device__ __forceinline__ u64 add2(u64 a, u64 b) {
    u64 d; asm("add.rn.f32x2 %0, %1, %2;" : "=l"(d) : "l"(a), "l"(b)); return d;
}
__device__ __forceinline__ float2 unpk(u64 d) {
    float2 f; asm("mov.b64 {%0, %1}, %2;" : "=f"(f.x), "=f"(f.y) : "l"(d)); return f;
}

// Per-warp state: u64 = (batch b0, batch b1) pair, indexed by column.
// Layout is contiguous so one base pointer + immediates addresses everything.
struct __align__(16) WarpState {
    u64 hf[HID];    // float units:   0..63   (u64 idx  0..31)
    u64 hp[HID];    //               64..127
    u64 hs0[HID];   //              128..191
    u64 hs1[HID];   //              192..255
    u64 hs2[HID];   //              256..319
    u64 xf[DF];     //              320..335
    u64 xp[DP];     //              336..351
    u64 xs[DS];     //              352..399
};
// float-unit offsets for group-g scalar views:
#define OF_HF  0
#define OF_HP  64
#define OF_HS0 128
#define OF_HS1 192
#define OF_HS2 256
#define OF_XS  352

__global__ void __launch_bounds__(NTHREADS, 1)
chive_kernel(const float* __restrict__ frnn, const float* __restrict__ phrnn,
             const float* __restrict__ syl,
             const float* __restrict__ Wxf, const float* __restrict__ Whf,
             const float* __restrict__ bfv,
             const float* __restrict__ Wxp, const float* __restrict__ Whp,
             const float* __restrict__ bpv,
             const float* __restrict__ Wxs, const float* __restrict__ Whs,
             const float* __restrict__ bsv,
             const int* __restrict__ fclock, const int* __restrict__ pclock,
             const int* __restrict__ sfreq,
             float* __restrict__ out)
{
    __shared__ unsigned char flags_sm[T_LEN];
    __shared__ WarpState wst[WARPS_PER_CTA];

    const int tid = threadIdx.x;
    for (int t = tid; t < T_LEN; t += NTHREADS) {
        int fl = ((t % (fclock[t] + 1)) == 0) ? 1 : 0;
        if ((t % (pclock[t] + 1)) == 0) fl |= 2;
        if (sfreq[t] == 1) fl |= 4;
        flags_sm[t] = (unsigned char)fl;
    }
    __syncthreads();

    const int warp = tid >> 5;
    const int lane = tid & 31;
    const int g    = lane >> 4;       // batch group (0/1): scalar batch b0+g
    const int l    = lane & 15;       // j-lane: owns columns l and l+16 in s-cell
    const int b0 = (blockIdx.x * WARPS_PER_CTA + warp) * 2;
    if (b0 >= B_LEN) return;          // after the only __syncthreads

    WarpState& S = wst[warp];
    S.hf[lane] = 0ull; S.hp[lane] = 0ull;
    S.hs0[lane] = 0ull; S.hs1[lane] = 0ull; S.hs2[lane] = 0ull;

    // Group-g scalar view of the whole state block (single base register).
    float* bg = ((float*)&S) + g;

    // f/p cells: R1-style single-column register weights (lane = column).
    float wxf[DF], whf[HID], wxp[DP], whp[HID];
    #pragma unroll
    for (int i = 0; i < DF; i++)  wxf[i] = Wxf[i * HID + lane];
    #pragma unroll
    for (int k = 0; k < HID; k++) whf[k] = Whf[k * HID + lane];
    #pragma unroll
    for (int i = 0; i < DP; i++)  wxp[i] = Wxp[i * HID + lane];
    #pragma unroll
    for (int k = 0; k < HID; k++) whp[k] = Whp[k * HID + lane];
    const float rbf = bfv[lane], rbp = bpv[lane];

    // s-cell: two weight columns per lane (cols l and l+16) in registers.
    float wxsl[HID], wxsh[HID], whsl[HID], whsh[HID];
    #pragma unroll
    for (int k = 0; k < HID; k++) {
        wxsl[k] = Wxs[k * HID + l];
        wxsh[k] = Wxs[k * HID + l + 16];
        whsl[k] = Whs[k * HID + l];
        whsh[k] = Whs[k * HID + l + 16];
    }
    const float bs_l = bsv[l], bs_h = bsv[l + 16];

    // Gated 1-step-ahead input prefetch (R1 pattern; DRAM is 2.6% busy).
    float f0 = 0.f, f1 = 0.f, p0 = 0.f, p1 = 0.f, s0 = 0.f, s1 = 0.f;
    {
        const int fl0 = flags_sm[0];
        if ((fl0 & 1) && lane < DF) {
            f0 = frnn[(size_t)b0 * DF + lane];
            f1 = frnn[(size_t)(b0 + 1) * DF + lane];
        }
        if ((fl0 & 2) && lane < DP) {
            p0 = phrnn[(size_t)b0 * DP + lane];
            p1 = phrnn[(size_t)(b0 + 1) * DP + lane];
        }
        if ((fl0 & 4) && lane < DS) {
            s0 = syl[(size_t)b0 * DS + lane];
            s1 = syl[(size_t)(b0 + 1) * DS + lane];
        }
    }
    __syncwarp();

    for (int t = 0; t < T_LEN; t++) {
        const int fl = flags_sm[t];

        // Prefetch inputs for t+1 (gated by its flags).
        float nf0 = 0.f, nf1 = 0.f, np0 = 0.f, np1 = 0.f, ns0 = 0.f, ns1 = 0.f;
        if (t + 1 < T_LEN) {
            const int nfl = flags_sm[t + 1];
            const size_t base = (size_t)(t + 1) * B_LEN;
            if ((nfl & 1) && lane < DF) {
                nf0 = frnn[(base + b0) * DF + lane];
                nf1 = frnn[(base + b0 + 1) * DF + lane];
            }
            if ((nfl & 2) && lane < DP) {
                np0 = phrnn[(base + b0) * DP + lane];
                np1 = phrnn[(base + b0 + 1) * DP + lane];
            }
            if ((nfl & 4) && lane < DS) {
                ns0 = syl[(base + b0) * DS + lane];
                ns1 = syl[(base + b0 + 1) * DS + lane];
            }
        }

        if (fl) {
            if ((fl & 1) && lane < DF) S.xf[lane] = pack2(f0, f1);
            if ((fl & 2) && lane < DP) S.xp[lane] = pack2(p0, p1);
            if ((fl & 4) && lane < DS) S.xs[lane] = pack2(s0, s1);
            __syncwarp();   // stage visible; fences prior-step state writes

            const bool wf = (fl & 1) != 0, wp = (fl & 2) != 0;
            u64 nhf = 0ull, nhp = 0ull;

            if (wf) {   // lane = column, u64 = batch pair
                u64 a = pk2(rbf), c = 0ull;
                #pragma unroll
                for (int i = 0; i < DF; i++)
                    fma2(a, S.xf[i], pk2(wxf[i]));
                #pragma unroll
                for (int k = 0; k < HID; k++)
                    fma2(c, S.hf[k], pk2(whf[k]));
                const float2 u = unpk(add2(a, c));
                nhf = pack2(tanh_fast(u.x), tanh_fast(u.y));
            }
            if (wp) {
                u64 a = pk2(rbp), c = 0ull;
                #pragma unroll
                for (int i = 0; i < DP; i++)
                    fma2(a, S.xp[i], pk2(wxp[i]));
                #pragma unroll
                for (int k = 0; k < HID; k++)
                    fma2(c, S.hp[k], pk2(whp[k]));
                const float2 u = unpk(add2(a, c));
                nhp = pack2(tanh_fast(u.x), tanh_fast(u.y));
            }
            if (wf || wp) {
                __syncwarp();   // all lanes finished reading old hf/hp
                if (wf) S.hf[lane] = nhf;
                if (wp) S.hp[lane] = nhp;
                __syncwarp();   // new hf/hp visible for s-cell
            }

            if (fl & 4) {
                // Group-split scalar s-cell: lane (g,l) computes columns l and
                // l+16 of all 3 rows for batch b0+g. Each state read is a
                // 2-address LDS.32 = 1 wavefront serving the whole warp.
                float a0l = bs_l, a0h = bs_h;   // row0: x = hf
                float a1l = bs_l, a1h = bs_h;   // row1: x = hp
                float a2l = bs_l, a2h = bs_h;   // row2: x = xs
                #pragma unroll
                for (int k = 0; k < HID; k++) {
                    const float hfv = bg[OF_HF  + 2 * k];
                    const float hpv = bg[OF_HP  + 2 * k];
                    const float h0v = bg[OF_HS0 + 2 * k];
                    const float h1v = bg[OF_HS1 + 2 * k];
                    const float h2v = bg[OF_HS2 + 2 * k];
                    const float wxl = wxsl[k], wxh = wxsh[k];
                    const float whl = whsl[k], whh = whsh[k];
                    a0l = fmaf(hfv, wxl, a0l);  a0h = fmaf(hfv, wxh, a0h);
                    a1l = fmaf(hpv, wxl, a1l);  a1h = fmaf(hpv, wxh, a1h);
                    a0l = fmaf(h0v, whl, a0l);  a0h = fmaf(h0v, whh, a0h);
                    a1l = fmaf(h1v, whl, a1l);  a1h = fmaf(h1v, whh, a1h);
                    a2l = fmaf(h2v, whl, a2l);  a2h = fmaf(h2v, whh, a2h);
                }
                #pragma unroll
                for (int k = 0; k < DS; k++) {  // padded cols 24..31 are zero
                    const float xv = bg[OF_XS + 2 * k];
                    a2l = fmaf(xv, wxsl[k], a2l);
                    a2h = fmaf(xv, wxsh[k], a2h);
                }
                const float o0l = tanh_fast(a0l), o0h = tanh_fast(a0h);
                const float o1l = tanh_fast(a1l), o1h = tanh_fast(a1h);
                const float o2l = tanh_fast(a2l), o2h = tanh_fast(a2h);
                __syncwarp();   // all lanes finished reading old hs
                bg[OF_HS0 + 2 * l] = o0l;  bg[OF_HS0 + 2 * (l + 16)] = o0h;
                bg[OF_HS1 + 2 * l] = o1l;  bg[OF_HS1 + 2 * (l + 16)] = o1h;
                bg[OF_HS2 + 2 * l] = o2l;  bg[OF_HS2 + 2 * (l + 16)] = o2h;
            }
        }

        f0 = nf0; f1 = nf1; p0 = np0; p1 = np1; s0 = ns0; s1 = ns1;
    }

    __syncwarp();   // hs written piecewise — fence before epilogue reads
    // Emit final h_s [3, B, H]; lane reads column=lane for both batches.
    const float2 r0 = unpk(S.hs0[lane]);
    const float2 r1 = unpk(S.hs1[lane]);
    const float2 r2 = unpk(S.hs2[lane]);
    out[((size_t)0 * B_LEN + b0)     * HID + lane] = r0.x;
    out[((size_t)0 * B_LEN + b0 + 1) * HID + lane] = r0.y;
    out[((size_t)1 * B_LEN + b0)     * HID + lane] = r1.x;
    out[((size_t)1 * B_LEN + b0 + 1) * HID + lane] = r1.y;
    out[((size_t)2 * B_LEN + b0)     * HID + lane] = r2.x;
    out[((size_t)2 * B_LEN + b0 + 1) * HID + lane] = r2.y;
}

extern "C" void kernel_launch(void* const* d_in, const int* in_sizes, int n_in,
                              void* d_out, int out_size) {
    (void)in_sizes; (void)n_in; (void)out_size;
    chive_kernel<<<NCTAS, NTHREADS>>>(
        (const float*)d_in[0],  (const float*)d_in[1],  (const float*)d_in[2],
        (const float*)d_in[3],  (const float*)d_in[4],  (const float*)d_in[5],
        (const float*)d_in[6],  (const float*)d_in[7],  (const float*)d_in[8],
        (const float*)d_in[9],  (const float*)d_in[10], (const float*)d_in[11],
        (const int*)d_in[12],   (const int*)d_in[13],   (const int*)d_in[14],
        (float*)d_out);
}

// round 16
// speedup vs baseline: 1.5546x; 1.0460x over previous
#include <cuda_runtime.h>

#define T_LEN 2048
#define B_LEN 2048
#define HID   32
#define DF    8
#define DP    8
#define DS    24
#define WARPS_PER_CTA 7
#define NTHREADS (WARPS_PER_CTA * 32)
#define NCTAS 147      // 147*7 = 1029 warps; 1024 active (B/2)

typedef unsigned long long u64;

__device__ __forceinline__ float tanh_fast(float x) {
    float y; asm("tanh.approx.f32 %0, %1;" : "=f"(y) : "f"(x)); return y;
}
__device__ __forceinline__ u64 pk2(float w) {            // (w, w)
    u64 d; asm("mov.b64 %0, {%1, %1};" : "=l"(d) : "f"(w)); return d;
}
__device__ __forceinline__ u64 pack2(float lo, float hi) {
    u64 d; asm("mov.b64 %0, {%1, %2};" : "=l"(d) : "f"(lo), "f"(hi)); return d;
}
__device__ __forceinline__ void fma2(u64& a, u64 x, u64 w) {
    asm("fma.rn.f32x2 %0, %1, %2, %0;" : "+l"(a) : "l"(x), "l"(w));
}
__device__ __forceinline__ u64 add2(u64 a, u64 b) {
    u64 d; asm("add.rn.f32x2 %0, %1, %2;" : "=l"(d) : "l"(a), "l"(b)); return d;
}
__device__ __forceinline__ float2 unpk(u64 d) {
    float2 f; asm("mov.b64 {%0, %1}, %2;" : "=f"(f.x), "=f"(f.y) : "l"(d)); return f;
}

// AoS per-k state: one 48-byte record per hidden index k.
// 16B-aligned pairs: (hf,hp) @0, (hs0,hs1) @16, (hs2,xs) @32 -> 3 LDS.128/k.
struct __align__(16) KState {
    u64 hf, hp;     // offset 0, 8
    u64 hs0, hs1;   // offset 16, 24
    u64 hs2, xs;    // offset 32, 40  (xs: rows k<DS staged, k>=DS stay 0)
};
struct __align__(16) XFP { u64 xf, xp; };

struct WarpSmem {
    KState st[HID];   // 1536 B
    XFP    xfp[DF];   // 128 B
};

__global__ void __launch_bounds__(NTHREADS, 1)
chive_kernel(const float* __restrict__ frnn, const float* __restrict__ phrnn,
             const float* __restrict__ syl,
             const float* __restrict__ Wxf, const float* __restrict__ Whf,
             const float* __restrict__ bfv,
             const float* __restrict__ Wxp, const float* __restrict__ Whp,
             const float* __restrict__ bpv,
             const float* __restrict__ Wxs, const float* __restrict__ Whs,
             const float* __restrict__ bsv,
             const int* __restrict__ fclock, const int* __restrict__ pclock,
             const int* __restrict__ sfreq,
             float* __restrict__ out)
{
    __shared__ unsigned char flags_sm[T_LEN];
    __shared__ WarpSmem wsm[WARPS_PER_CTA];

    const int tid = threadIdx.x;
    for (int t = tid; t < T_LEN; t += NTHREADS) {
        int fl = ((t % (fclock[t] + 1)) == 0) ? 1 : 0;
        if ((t % (pclock[t] + 1)) == 0) fl |= 2;
        if (sfreq[t] == 1) fl |= 4;
        flags_sm[t] = (unsigned char)fl;
    }
    __syncthreads();

    const int warp = tid >> 5;
    const int lane = tid & 31;
    const int b0 = (blockIdx.x * WARPS_PER_CTA + warp) * 2;
    if (b0 >= B_LEN) return;   // after the only __syncthreads

    KState* st = wsm[warp].st;
    XFP*    xfp = wsm[warp].xfp;

    // Zero entire state record (incl. xs rows >= DS which stay 0 forever).
    st[lane].hf = 0ull; st[lane].hp = 0ull;
    st[lane].hs0 = 0ull; st[lane].hs1 = 0ull;
    st[lane].hs2 = 0ull; st[lane].xs = 0ull;

    // f/p weights: scalar per-lane columns (pk2 on use; ALU pipe is idle).
    float wxf[DF], whf[HID], wxp[DP], whp[HID];
    #pragma unroll
    for (int i = 0; i < DF; i++)  wxf[i] = Wxf[i * HID + lane];
    #pragma unroll
    for (int k = 0; k < HID; k++) whf[k] = Whf[k * HID + lane];
    #pragma unroll
    for (int i = 0; i < DP; i++)  wxp[i] = Wxp[i * HID + lane];
    #pragma unroll
    for (int k = 0; k < HID; k++) whp[k] = Whp[k * HID + lane];
    const float rbf = bfv[lane], rbp = bpv[lane];

    // s-cell weights pre-packed (w,w) in registers: no pk2 in the hot loop.
    u64 wxs2[HID], whs2[HID];
    #pragma unroll
    for (int k = 0; k < HID; k++) {
        wxs2[k] = pk2(Wxs[k * HID + lane]);
        whs2[k] = pk2(Whs[k * HID + lane]);
    }
    const u64 bs2 = pk2(bsv[lane]);

    // Gated 1-step-ahead input prefetch (R1 pattern).
    float f0 = 0.f, f1 = 0.f, p0 = 0.f, p1 = 0.f, s0 = 0.f, s1 = 0.f;
    {
        const int fl0 = flags_sm[0];
        if ((fl0 & 1) && lane < DF) {
            f0 = frnn[(size_t)b0 * DF + lane];
            f1 = frnn[(size_t)(b0 + 1) * DF + lane];
        }
        if ((fl0 & 2) && lane < DP) {
            p0 = phrnn[(size_t)b0 * DP + lane];
            p1 = phrnn[(size_t)(b0 + 1) * DP + lane];
        }
        if ((fl0 & 4) && lane < DS) {
            s0 = syl[(size_t)b0 * DS + lane];
            s1 = syl[(size_t)(b0 + 1) * DS + lane];
        }
    }
    __syncwarp();

    for (int t = 0; t < T_LEN; t++) {
        const int fl = flags_sm[t];

        // Prefetch inputs for t+1 (gated by its flags).
        float nf0 = 0.f, nf1 = 0.f, np0 = 0.f, np1 = 0.f, ns0 = 0.f, ns1 = 0.f;
        if (t + 1 < T_LEN) {
            const int nfl = flags_sm[t + 1];
            const size_t base = (size_t)(t + 1) * B_LEN;
            if ((nfl & 1) && lane < DF) {
                nf0 = frnn[(base + b0) * DF + lane];
                nf1 = frnn[(base + b0 + 1) * DF + lane];
            }
            if ((nfl & 2) && lane < DP) {
                np0 = phrnn[(base + b0) * DP + lane];
                np1 = phrnn[(base + b0 + 1) * DP + lane];
            }
            if ((nfl & 4) && lane < DS) {
                ns0 = syl[(base + b0) * DS + lane];
                ns1 = syl[(base + b0 + 1) * DS + lane];
            }
        }

        if (fl) {
            // Stage this step's inputs.
            if (lane < DF) {
                XFP v;
                v.xf = (fl & 1) ? pack2(f0, f1) : xfp[lane].xf;
                v.xp = (fl & 2) ? pack2(p0, p1) : xfp[lane].xp;
                if (fl & 3) xfp[lane] = v;      // one STS.128
            }
            if ((fl & 4) && lane < DS) st[lane].xs = pack2(s0, s1);
            __syncwarp();   // stage visible; fences prior-step state writes

            const bool wf = (fl & 1) != 0, wp = (fl & 2) != 0;

            if (wf || wp) {
                // Merged f+p cell: one LDS.128 (hf,hp) per k feeds both.
                u64 af = pk2(rbf), ap = pk2(rbp);
                #pragma unroll
                for (int i = 0; i < DF; i++) {
                    const ulonglong2 x = *(const ulonglong2*)&xfp[i];
                    fma2(af, x.x, pk2(wxf[i]));
                    fma2(ap, x.y, pk2(wxp[i]));
                }
                #pragma unroll
                for (int k = 0; k < HID; k++) {
                    const ulonglong2 h = *(const ulonglong2*)&st[k].hf;
                    fma2(af, h.x, pk2(whf[k]));
                    fma2(ap, h.y, pk2(whp[k]));
                }
                const float2 uf = unpk(af), up = unpk(ap);
                const u64 nhf = pack2(tanh_fast(uf.x), tanh_fast(uf.y));
                const u64 nhp = pack2(tanh_fast(up.x), tanh_fast(up.y));
                __syncwarp();   // all lanes finished reading old hf/hp
                if (wf) st[lane].hf = nhf;
                if (wp) st[lane].hp = nhp;
                __syncwarp();   // new hf/hp visible for s-cell
            }

            if (fl & 4) {
                // s-cell: 3 LDS.128 per k cover all 6 state streams.
                u64 a0 = bs2, c0 = 0ull;   // row0: x = hf
                u64 a1 = bs2, c1 = 0ull;   // row1: x = hp
                u64 a2 = bs2, c2 = 0ull;   // row2: x = xs (rows >= DS are 0)
                #pragma unroll
                for (int k = 0; k < HID; k++) {
                    const ulonglong2 v01 = *(const ulonglong2*)&st[k].hf;
                    const ulonglong2 v23 = *(const ulonglong2*)&st[k].hs0;
                    const ulonglong2 v45 = *(const ulonglong2*)&st[k].hs2;
                    const u64 wx = wxs2[k], wh = whs2[k];
                    fma2(a0, v01.x, wx);
                    fma2(a1, v01.y, wx);
                    fma2(c0, v23.x, wh);
                    fma2(c1, v23.y, wh);
                    fma2(c2, v45.x, wh);
                    fma2(a2, v45.y, wx);
                }
                const float2 u0 = unpk(add2(a0, c0));
                const float2 u1 = unpk(add2(a1, c1));
                const float2 u2 = unpk(add2(a2, c2));
                const u64 o0 = pack2(tanh_fast(u0.x), tanh_fast(u0.y));
                const u64 o1 = pack2(tanh_fast(u1.x), tanh_fast(u1.y));
                const u64 o2 = pack2(tanh_fast(u2.x), tanh_fast(u2.y));
                __syncwarp();   // all lanes finished reading old hs
                *(ulonglong2*)&st[lane].hs0 = make_ulonglong2(o0, o1); // STS.128
                st[lane].hs2 = o2;
            }
        }

        f0 = nf0; f1 = nf1; p0 = np0; p1 = np1; s0 = ns0; s1 = ns1;
    }

    __syncwarp();   // fence last state writes before epilogue reads
    const float2 r0 = unpk(st[lane].hs0);
    const float2 r1 = unpk(st[lane].hs1);
    const float2 r2 = unpk(st[lane].hs2);
    out[((size_t)0 * B_LEN + b0)     * HID + lane] = r0.x;
    out[((size_t)0 * B_LEN + b0 + 1) * HID + lane] = r0.y;
    out[((size_t)1 * B_LEN + b0)     * HID + lane] = r1.x;
    out[((size_t)1 * B_LEN + b0 + 1) * HID + lane] = r1.y;
    out[((size_t)2 * B_LEN + b0)     * HID + lane] = r2.x;
    out[((size_t)2 * B_LEN + b0 + 1) * HID + lane] = r2.y;
}

extern "C" void kernel_launch(void* const* d_in, const int* in_sizes, int n_in,
                              void* d_out, int out_size) {
    (void)in_sizes; (void)n_in; (void)out_size;
    chive_kernel<<<NCTAS, NTHREADS>>>(
        (const float*)d_in[0],  (const float*)d_in[1],  (const float*)d_in[2],
        (const float*)d_in[3],  (const float*)d_in[4],  (const float*)d_in[5],
        (const float*)d_in[6],  (const float*)d_in[7],  (const float*)d_in[8],
        (const float*)d_in[9],  (const float*)d_in[10], (const float*)d_in[11],
        (const int*)d_in[12],   (const int*)d_in[13],   (const int*)d_in[14],
        (float*)d_out);
}